// round 14
// baseline (speedup 1.0000x reference)
#include <cuda_runtime.h>
#include <cuda_bf16.h>

// Problem constants
#define B_    16
#define C_    64
#define H_    256
#define W_    256
#define W4_   (W_ / 4)             // 64
#define HW_   (H_ * W_)            // 65536
#define HW4_  (HW_ / 4)            // 16384
#define BHW_  (B_ * HW_)           // 1048576
#define K_    11
#define P_    5
#define EPS_  1e-6f

#define CSEG_ 8                    // channel split factor (measured: 79.8us vs 80.9 @4)
#define CPT_  (C_ / CSEG_)         // 8 channels per segment
#define RBT_  128                  // reduce block threads (11 blk/SM vs 5 @256)
#define RPT_  2                    // output rows per thread in vblur

// Scratch: 3 maps (sxx, sxy, syy) before/after horizontal blur. 12 MiB each.
// d_S MUST stay L2-resident (48 MiB partial buffers regressed in R7).
// INVARIANT: d_S is zero at entry (zero-init at load; vblur — running after
// hblur, the only reader — re-zeroes it every call).
__device__ float d_S[3 * BHW_];
__device__ float d_T[3 * BHW_];

// ---------------------------------------------------------------------------
// Kernel 1: channel reduction, 8-way split over C, 128-thread blocks.
// Epilogue: red.global.add.v4.f32 into the L2-resident d_S.
// ---------------------------------------------------------------------------
__device__ __forceinline__ void red_v4(float* p, float4 v) {
    asm volatile("red.global.add.v4.f32 [%0], {%1, %2, %3, %4};"
                 :: "l"(p), "f"(v.x), "f"(v.y), "f"(v.z), "f"(v.w) : "memory");
}

__global__ void __launch_bounds__(RBT_) k_reduce(const float4* __restrict__ x,
                                                 const float4* __restrict__ y) {
    int idx = blockIdx.x * RBT_ + threadIdx.x;         // 0 .. CSEG*B*HW4-1
    int seg = idx >> 18;                               // channel segment 0..7
    int pos = idx & (B_ * HW4_ - 1);                   // float4 position
    int b   = pos >> 14;
    int p   = pos & (HW4_ - 1);

    const float4* xp = x + (size_t)b * (C_ * HW4_) + (size_t)(seg * CPT_) * HW4_ + p;
    const float4* yp = y + (size_t)b * (C_ * HW4_) + (size_t)(seg * CPT_) * HW4_ + p;

    float4 axx = make_float4(0.f, 0.f, 0.f, 0.f);
    float4 axy = make_float4(0.f, 0.f, 0.f, 0.f);
    float4 ayy = make_float4(0.f, 0.f, 0.f, 0.f);

#pragma unroll
    for (int c = 0; c < CPT_; c += 4) {
        float4 xv0 = __ldcs(xp + (c + 0) * HW4_);
        float4 xv1 = __ldcs(xp + (c + 1) * HW4_);
        float4 xv2 = __ldcs(xp + (c + 2) * HW4_);
        float4 xv3 = __ldcs(xp + (c + 3) * HW4_);
        float4 yv0 = __ldcs(yp + (c + 0) * HW4_);
        float4 yv1 = __ldcs(yp + (c + 1) * HW4_);
        float4 yv2 = __ldcs(yp + (c + 2) * HW4_);
        float4 yv3 = __ldcs(yp + (c + 3) * HW4_);

        axx.x += xv0.x*xv0.x; axx.y += xv0.y*xv0.y; axx.z += xv0.z*xv0.z; axx.w += xv0.w*xv0.w;
        axy.x += xv0.x*yv0.x; axy.y += xv0.y*yv0.y; axy.z += xv0.z*yv0.z; axy.w += xv0.w*yv0.w;
        ayy.x += yv0.x*yv0.x; ayy.y += yv0.y*yv0.y; ayy.z += yv0.z*yv0.z; ayy.w += yv0.w*yv0.w;

        axx.x += xv1.x*xv1.x; axx.y += xv1.y*xv1.y; axx.z += xv1.z*xv1.z; axx.w += xv1.w*xv1.w;
        axy.x += xv1.x*yv1.x; axy.y += xv1.y*yv1.y; axy.z += xv1.z*yv1.z; axy.w += xv1.w*yv1.w;
        ayy.x += yv1.x*yv1.x; ayy.y += yv1.y*yv1.y; ayy.z += yv1.z*yv1.z; ayy.w += yv1.w*yv1.w;

        axx.x += xv2.x*xv2.x; axx.y += xv2.y*xv2.y; axx.z += xv2.z*xv2.z; axx.w += xv2.w*xv2.w;
        axy.x += xv2.x*yv2.x; axy.y += xv2.y*yv2.y; axy.z += xv2.z*yv2.z; axy.w += xv2.w*yv2.w;
        ayy.x += yv2.x*yv2.x; ayy.y += yv2.y*yv2.y; ayy.z += yv2.z*yv2.z; ayy.w += yv2.w*yv2.w;

        axx.x += xv3.x*xv3.x; axx.y += xv3.y*xv3.y; axx.z += xv3.z*xv3.z; axx.w += xv3.w*xv3.w;
        axy.x += xv3.x*yv3.x; axy.y += xv3.y*yv3.y; axy.z += xv3.z*yv3.z; axy.w += xv3.w*yv3.w;
        ayy.x += yv3.x*yv3.x; ayy.y += yv3.y*yv3.y; ayy.z += yv3.z*yv3.z; ayy.w += yv3.w*yv3.w;
    }

    int o = pos * 4;
    red_v4(&d_S[o],            axx);
    red_v4(&d_S[BHW_ + o],     axy);
    red_v4(&d_S[2 * BHW_ + o], ayy);
}

// ---------------------------------------------------------------------------
// Kernel 2: horizontal 11-tap blur, smem row-staged. Each d_S float4 is
// loaded from L2 exactly once; taps come from conflict-free LDS.128.
// g1[i] = gauss[5][i] * rsqrt(gauss[5][5]) recovers the exact 1D factor.
// ---------------------------------------------------------------------------
__global__ void k_hblur(const float* __restrict__ gauss) {
    __shared__ float  g1[K_];
    __shared__ float4 s4[4][68];           // [-2..65] stored at +2; pads zeroed

    int tid = threadIdx.x;
    if (tid < K_)
        g1[tid] = gauss[5 * K_ + tid] * rsqrtf(gauss[5 * K_ + 5]);

    int rl = tid >> 6;                     // row within block, 0..3
    int c4 = tid & 63;                     // float4 column, 0..63

    int rowtask = blockIdx.x * 4 + rl;     // 0 .. 3*B*H-1 (map-major linear)
    int gbase   = rowtask * W4_;           // global float4 index of row start

    const float4* S4 = reinterpret_cast<const float4*>(d_S);
    s4[rl][c4 + 2] = S4[gbase + c4];
    if (tid < 16) {                        // 4 rows x {0,1,66,67} pads
        int r  = tid >> 2;
        int pi = tid & 3;
        s4[r][(pi < 2) ? pi : 64 + pi] = make_float4(0.f, 0.f, 0.f, 0.f);
    }
    __syncthreads();

    float s[20];
#pragma unroll
    for (int j = 0; j < 5; j++) {          // logical cols c4-2 .. c4+2
        float4 v = s4[rl][c4 + j];
        s[4*j+0] = v.x; s[4*j+1] = v.y; s[4*j+2] = v.z; s[4*j+3] = v.w;
    }

    float4 acc = make_float4(0.f, 0.f, 0.f, 0.f);
#pragma unroll
    for (int k = 0; k < K_; k++) {
        float g = g1[k];
        acc.x += g * s[k + 3];
        acc.y += g * s[k + 4];
        acc.z += g * s[k + 5];
        acc.w += g * s[k + 6];
    }
    reinterpret_cast<float4*>(d_T)[gbase + c4] = acc;
}

// ---------------------------------------------------------------------------
// Kernel 3: vertical 11-tap blur + cosine combine, 2 output rows per thread.
// 256-thread blocks cover 4 consecutive row-groups x 64 w4 for L1 row reuse.
// Also re-zeroes d_S (6 float4/thread) to maintain the entry invariant.
// ---------------------------------------------------------------------------
__global__ void k_vblur(const float* __restrict__ gauss, float4* __restrict__ out) {
    __shared__ float g1[K_];
    if (threadIdx.x < K_)
        g1[threadIdx.x] = gauss[5 * K_ + threadIdx.x] * rsqrtf(gauss[5 * K_ + 5]);
    __syncthreads();

    int idx = blockIdx.x * blockDim.x + threadIdx.x;    // 0 .. BHW/4/RPT-1
    int w4 = idx & (W4_ - 1);
    int hg = (idx >> 6) & (H_ / RPT_ - 1);              // row-group 0..127
    int b  = idx >> 13;
    int h0 = hg * RPT_;

    const float4* T4  = reinterpret_cast<const float4*>(d_T);
    int           col = b * HW4_ + w4;

    float4 sxx[RPT_], sxy[RPT_], syy[RPT_];
#pragma unroll
    for (int o = 0; o < RPT_; o++) {
        sxx[o] = make_float4(0.f, 0.f, 0.f, 0.f);
        sxy[o] = make_float4(0.f, 0.f, 0.f, 0.f);
        syy[o] = make_float4(0.f, 0.f, 0.f, 0.f);
    }

#pragma unroll
    for (int r = 0; r < RPT_ + 2 * P_; r++) {
        int hh = h0 + r - P_;
        if ((unsigned)hh < (unsigned)H_) {
            int off  = col + hh * W4_;
            float4 a = T4[off];
            float4 c = T4[off + BHW_ / 4];
            float4 d = T4[off + 2 * (BHW_ / 4)];
#pragma unroll
            for (int o = 0; o < RPT_; o++) {
                int k = r - o;
                if (k >= 0 && k < K_) {
                    float g = g1[k];
                    sxx[o].x += g*a.x; sxx[o].y += g*a.y; sxx[o].z += g*a.z; sxx[o].w += g*a.w;
                    sxy[o].x += g*c.x; sxy[o].y += g*c.y; sxy[o].z += g*c.z; sxy[o].w += g*c.w;
                    syy[o].x += g*d.x; syy[o].y += g*d.y; syy[o].z += g*d.z; syy[o].w += g*d.w;
                }
            }
        }
    }

#pragma unroll
    for (int o = 0; o < RPT_; o++) {
        float4 r;
        r.x = sxy[o].x / (sqrtf(sxx[o].x) * sqrtf(syy[o].x) + EPS_);
        r.y = sxy[o].y / (sqrtf(sxx[o].y) * sqrtf(syy[o].y) + EPS_);
        r.z = sxy[o].z / (sqrtf(sxx[o].z) * sqrtf(syy[o].z) + EPS_);
        r.w = sxy[o].w / (sqrtf(sxx[o].w) * sqrtf(syy[o].w) + EPS_);
        out[col + (h0 + o) * W4_] = r;
    }

    // Re-zero d_S for the next invocation (entry invariant). 131072 threads x
    // 6 float4 = 3*BHW floats. Safe: hblur (the only d_S reader) already ran.
    float4* S4 = reinterpret_cast<float4*>(d_S);
    float4 z = make_float4(0.f, 0.f, 0.f, 0.f);
#pragma unroll
    for (int j = 0; j < 6; j++)
        S4[6 * idx + j] = z;
}

// ---------------------------------------------------------------------------
extern "C" void kernel_launch(void* const* d_in, const int* in_sizes, int n_in,
                              void* d_out, int out_size) {
    const float4* x     = (const float4*)d_in[0];
    const float4* y     = (const float4*)d_in[1];
    const float*  gauss = (const float*)d_in[2];
    float4*       out   = (float4*)d_out;

    k_reduce<<<CSEG_ * B_ * HW4_ / RBT_, RBT_>>>(x, y);             // 16384 blocks
    k_hblur <<<3 * B_ * H_ / 4, 256>>>(gauss);                      // 3072 blocks
    k_vblur <<<BHW_ / 4 / RPT_ / 256, 256>>>(gauss, out);           // 512 blocks
}